// round 13
// baseline (speedup 1.0000x reference)
#include <cuda_runtime.h>
#include <cuda_fp16.h>
#include <cuda_bf16.h>
#include <cstdint>
#include <cstdlib>

#define NNODES 50000
#define E0     300000
#define ETOT   350000
#define FIN    78
#define FINP   96          // FIN padded to mult of 32
#define H1N    10
#define FH1    78
#define D1     (H1N*FH1)   // 780
#define H1S    784         // h1 row stride in halfs (1568B, 16B-aligned for cp.async)
#define D1P    800         // h1e row stride / GEMM2 K, mult of 32
#define FOUT   128
#define NGRAPH 256

// ---------------- scratch arena (phase-aliased; static device global) ----------------
#define ARENA_H1E_OFF ((size_t)NNODES * H1S * 2)          // 78,400,000
__device__ __align__(256) unsigned char g_arena[ARENA_H1E_OFF + (size_t)NNODES * D1P * 2];

__device__ __forceinline__ __half* p_h1()  { return (__half*)g_arena; }
__device__ __forceinline__ __half* p_h1e() { return (__half*)(g_arena + ARENA_H1E_OFF); }
__device__ __forceinline__ float*  p_h2()  { return (float*)g_arena; }
__device__ __forceinline__ float*  p_h2a() { return (float*)(g_arena + ARENA_H1E_OFF); }

__device__ __align__(16) __half g_xh [(size_t)NNODES * FINP];        // x fp16, K-padded
__device__ __align__(16) __half g_w1h[(size_t)FINP * D1P + 4096];    // W1 fp16 [96][800]
__device__ __align__(16) __half g_w2h[(size_t)D1P * FOUT + 4096];    // W2 fp16 [800][128]

__device__ float g_als1[NNODES * H1N];
__device__ float g_ald1[NNODES * H1N];
__device__ float g_als2[NNODES];
__device__ float g_ald2[NNODES];
__device__ unsigned g_max1[NNODES * H1N];
__device__ float    g_sum1[NNODES * H1N];
__device__ unsigned g_max2[NNODES];
__device__ float    g_sum2[NNODES];
__device__ float g_w1e[(size_t)ETOT * H1N];   // per-(CSR pos, head) exp weights, 14MB
__device__ float g_w2e[ETOT];
__device__ int   g_cnt[NNODES];
__device__ int   g_indptr[NNODES + 1];
__device__ int   g_cursor[NNODES];
__device__ int   g_csrc[ETOT];
__device__ int   g_cdst[ETOT];
__device__ float g_pool[NGRAPH * FOUT];

// monotone float<->uint map for atomicMax on floats (handles negatives)
__device__ __forceinline__ unsigned fmap(float f) {
    unsigned u = __float_as_uint(f);
    return (u & 0x80000000u) ? ~u : (u | 0x80000000u);
}
__device__ __forceinline__ float funmap(unsigned u) {
    return __uint_as_float((u & 0x80000000u) ? (u & 0x7fffffffu) : ~u);
}

__device__ __forceinline__ void cp16(void* sm, const void* gm, bool pred) {
    uint32_t s = (uint32_t)__cvta_generic_to_shared(sm);
    int sz = pred ? 16 : 0;
    asm volatile("cp.async.cg.shared.global [%0], [%1], 16, %2;" :: "r"(s), "l"(gm), "r"(sz));
}

// vector C-store helpers
__device__ __forceinline__ void st2(__half* p, float a, float b) {
    *(__half2*)p = __floats2half2_rn(a, b);
}
__device__ __forceinline__ void st2(float* p, float a, float b) {
    *(float2*)p = make_float2(a, b);
}

// ---------------- init: zero counts + pool + softmax accumulators ----------------
__global__ void k_init() {
    int i = blockIdx.x * blockDim.x + threadIdx.x;
    if (i < NNODES * H1N) { g_max1[i] = 0u; g_sum1[i] = 0.f; }
    if (i < NNODES) { g_max2[i] = 0u; g_sum2[i] = 0.f; g_cnt[i] = 0; }
    if (i < NGRAPH * FOUT) g_pool[i] = 0.0f;
}

// ---------------- CSR build ----------------
__global__ void k_count(const int* __restrict__ ei) {
    int e = blockIdx.x * blockDim.x + threadIdx.x;
    if (e >= ETOT) return;
    int dst = (e < E0) ? ei[E0 + e] : (e - E0);
    atomicAdd(&g_cnt[dst], 1);
}

__global__ void k_scan() {  // single block, 1024 threads
    const int ITEMS = (NNODES + 1023) / 1024;   // 49
    int t = threadIdx.x;
    int base = t * ITEMS;
    int sum = 0;
    for (int k = 0; k < ITEMS; k++) {
        int idx = base + k;
        if (idx < NNODES) sum += g_cnt[idx];
    }
    __shared__ int sh[1024];
    sh[t] = sum;
    __syncthreads();
    for (int off = 1; off < 1024; off <<= 1) {
        int v = (t >= off) ? sh[t - off] : 0;
        __syncthreads();
        sh[t] += v;
        __syncthreads();
    }
    int run = (t > 0) ? sh[t - 1] : 0;
    for (int k = 0; k < ITEMS; k++) {
        int idx = base + k;
        if (idx < NNODES) {
            g_indptr[idx] = run;
            g_cursor[idx] = run;
            run += g_cnt[idx];
        }
    }
    if (t == 1023) g_indptr[NNODES] = sh[1023];
}

__global__ void k_fill(const int* __restrict__ ei) {
    int e = blockIdx.x * blockDim.x + threadIdx.x;
    if (e >= ETOT) return;
    int src, dst;
    if (e < E0) { src = ei[e]; dst = ei[E0 + e]; }
    else        { src = e - E0; dst = e - E0; }
    int pos = atomicAdd(&g_cursor[dst], 1);
    g_csrc[pos] = src;
    g_cdst[pos] = dst;
}

// ---------------- fused fp32->fp16 conversion of x, W1, W2 (K-padded) -------------
__global__ void k_convert_all(const float* __restrict__ x, const float* __restrict__ W1,
                              const float* __restrict__ W2) {
    const int NX = NNODES * FINP;
    const int NW1 = FINP * D1P;
    const int NW2 = D1P * FOUT;
    int i = blockIdx.x * blockDim.x + threadIdx.x;
    int stride = gridDim.x * blockDim.x;
    for (int idx = i; idx < NX + NW1 + NW2; idx += stride) {
        if (idx < NX) {
            int r = idx / FINP, c = idx - r * FINP;
            float v = (c < FIN) ? x[(size_t)r * FIN + c] : 0.0f;
            g_xh[idx] = __float2half(v);
        } else if (idx < NX + NW1) {
            int j = idx - NX;
            int r = j / D1P, c = j - r * D1P;
            float v = (r < FIN && c < D1) ? W1[(size_t)r * D1 + c] : 0.0f;
            g_w1h[j] = __float2half(v);
        } else {
            int j = idx - NX - NW1;
            int r = j / FOUT, c = j - r * FOUT;
            float v = (r < D1) ? W2[(size_t)r * FOUT + c] : 0.0f;
            g_w2h[j] = __float2half(v);
        }
    }
}

// ---------------- tensor-core GEMM (BM=64, BN=128, BK=32, 3 CTA/SM) -------------
template<typename TC>
__global__ void __launch_bounds__(256, 3)
k_hgemm(const __half* __restrict__ A, const __half* __restrict__ B,
        TC* __restrict__ C, int M, int Nn, int K,
        int lda, int ldb, int ldc) {
    const int BM = 64, BK = 32;
    const int ASW = 40;
    const int BSW = 136;
    __shared__ __half As[2][BM * ASW];
    __shared__ __half Bs[2][BK * BSW];
    int tid = threadIdx.x, lane = tid & 31, warp = tid >> 5;
    int wm = (warp & 1) * 32, wn = (warp >> 1) * 32;
    int m0 = blockIdx.y * BM, n0 = blockIdx.x * 128;

    float acc[2][4][4];
#pragma unroll
    for (int a = 0; a < 2; a++)
#pragma unroll
        for (int b = 0; b < 4; b++)
#pragma unroll
            for (int c = 0; c < 4; c++) acc[a][b][c] = 0.f;

    const int ntiles = K / BK;

#define ISSUE_TILE(T, BUF) do {                                              \
        int kt_ = (T) * BK;                                                  \
        {                                                                    \
            int r = tid >> 2, c16 = (tid & 3) * 8;                           \
            int gm = m0 + r;                                                 \
            cp16(&As[BUF][r * ASW + c16], A + (size_t)gm * lda + kt_ + c16,  \
                 gm < M);                                                    \
        }                                                                    \
        _Pragma("unroll")                                                    \
        for (int q = 0; q < 2; q++) {                                        \
            int idx = tid + q * 256;                                         \
            int r = idx >> 4, c16 = (idx & 15) * 8;                          \
            int gn = n0 + c16;                                               \
            cp16(&Bs[BUF][r * BSW + c16], B + (size_t)(kt_ + r) * ldb + gn,  \
                 gn + 8 <= ldb);                                             \
        }                                                                    \
        asm volatile("cp.async.commit_group;");                              \
    } while (0)

    ISSUE_TILE(0, 0);
    for (int t = 0; t < ntiles; t++) {
        int buf = t & 1;
        if (t + 1 < ntiles) {
            ISSUE_TILE(t + 1, buf ^ 1);
            asm volatile("cp.async.wait_group 1;");
        } else {
            asm volatile("cp.async.wait_group 0;");
        }
        __syncthreads();

        const __half* as = As[buf];
        const __half* bs = Bs[buf];
#pragma unroll
        for (int ks = 0; ks < 2; ks++) {
            int kk = ks * 16;
            uint32_t af[2][4];
#pragma unroll
            for (int mf = 0; mf < 2; mf++) {
                int g = lane >> 3, j = lane & 7;
                int row = wm + mf * 16 + j + ((g & 1) << 3);
                int col = kk + ((g >> 1) << 3);
                uint32_t addr = (uint32_t)__cvta_generic_to_shared(as + row * ASW + col);
                asm volatile(
                    "ldmatrix.sync.aligned.m8n8.x4.shared.b16 {%0,%1,%2,%3}, [%4];"
                    : "=r"(af[mf][0]), "=r"(af[mf][1]), "=r"(af[mf][2]), "=r"(af[mf][3])
                    : "r"(addr));
            }
            uint32_t bf[4][2];
#pragma unroll
            for (int nfp = 0; nfp < 2; nfp++) {
                int nn0 = wn + nfp * 16;
                int g = lane >> 3, j = lane & 7;
                int row = kk + j + ((g & 1) << 3);
                int col = nn0 + ((g >> 1) << 3);
                uint32_t addr = (uint32_t)__cvta_generic_to_shared(bs + row * BSW + col);
                asm volatile(
                    "ldmatrix.sync.aligned.m8n8.x4.trans.shared.b16 {%0,%1,%2,%3}, [%4];"
                    : "=r"(bf[2 * nfp][0]), "=r"(bf[2 * nfp][1]),
                      "=r"(bf[2 * nfp + 1][0]), "=r"(bf[2 * nfp + 1][1])
                    : "r"(addr));
            }
#pragma unroll
            for (int mf = 0; mf < 2; mf++)
#pragma unroll
                for (int nf = 0; nf < 4; nf++) {
                    float* c = acc[mf][nf];
                    asm volatile(
                        "mma.sync.aligned.m16n8k16.row.col.f32.f16.f16.f32 "
                        "{%0,%1,%2,%3}, {%4,%5,%6,%7}, {%8,%9}, {%0,%1,%2,%3};"
                        : "+f"(c[0]), "+f"(c[1]), "+f"(c[2]), "+f"(c[3])
                        : "r"(af[mf][0]), "r"(af[mf][1]), "r"(af[mf][2]), "r"(af[mf][3]),
                          "r"(bf[nf][0]), "r"(bf[nf][1]));
                }
        }
        __syncthreads();
    }
#undef ISSUE_TILE

#pragma unroll
    for (int mf = 0; mf < 2; mf++)
#pragma unroll
        for (int nf = 0; nf < 4; nf++) {
            int r = m0 + wm + mf * 16 + (lane >> 2);
            int cbase = n0 + wn + nf * 8 + (lane & 3) * 2;
            const float* c = acc[mf][nf];
            if (cbase < Nn) {
                if (r < M)     st2(C + (size_t)r * ldc + cbase,       c[0], c[1]);
                if (r + 8 < M) st2(C + (size_t)(r + 8) * ldc + cbase, c[2], c[3]);
            }
        }
}

// ---------------- layer1 attention coefficients: warp per (node,head), half2 -------
__global__ void k_attn1(const float* __restrict__ a_src, const float* __restrict__ a_dst) {
    int n = blockIdx.x;
    int w = threadIdx.x >> 5;
    int lane = threadIdx.x & 31;
    const __half2* row = (const __half2*)(p_h1() + (size_t)n * H1S + w * FH1);
    const float* asw = a_src + w * FH1;
    const float* adw = a_dst + w * FH1;
    float s = 0.f, d = 0.f;
#pragma unroll
    for (int j = lane; j < 39; j += 32) {
        float2 f = __half22float2(row[j]);
        s += f.x * asw[2 * j] + f.y * asw[2 * j + 1];
        d += f.x * adw[2 * j] + f.y * adw[2 * j + 1];
    }
#pragma unroll
    for (int o = 16; o; o >>= 1) {
        s += __shfl_down_sync(0xffffffffu, s, o);
        d += __shfl_down_sync(0xffffffffu, d, o);
    }
    if (lane == 0) {
        g_als1[n * H1N + w] = s;
        g_ald1[n * H1N + w] = d;
    }
}

// ---------------- layer1 edge softmax, phase A: segment max -----------------------
__global__ void k_emax1() {
    int pos = blockIdx.x * blockDim.x + threadIdx.x;
    if (pos >= ETOT) return;
    int src = g_csrc[pos], dst = g_cdst[pos];
    const float* as = g_als1 + src * H1N;
    const float* ad = g_ald1 + dst * H1N;
    unsigned* mx = g_max1 + dst * H1N;
#pragma unroll
    for (int h = 0; h < H1N; h++) {
        float e = as[h] + ad[h];
        e = (e > 0.f) ? e : 0.2f * e;
        atomicMax(&mx[h], fmap(e));
    }
}

// ---------------- layer1 edge softmax, phase B: w = exp(e-max), segment sum -------
__global__ void k_esum1() {
    int pos = blockIdx.x * blockDim.x + threadIdx.x;
    if (pos >= ETOT) return;
    int src = g_csrc[pos], dst = g_cdst[pos];
    const float* as = g_als1 + src * H1N;
    const float* ad = g_ald1 + dst * H1N;
    const unsigned* mx = g_max1 + dst * H1N;
    float* sm = g_sum1 + dst * H1N;
    float* wout = g_w1e + (size_t)pos * H1N;
#pragma unroll
    for (int h = 0; h < H1N; h++) {
        float e = as[h] + ad[h];
        e = (e > 0.f) ? e : 0.2f * e;
        float w = __expf(e - funmap(mx[h]));
        wout[h] = w;
        atomicAdd(&sm[h], w);
    }
}

// ---------------- layer1 aggregate + bias + ELU (pure gather+FMA) -----------------
__global__ void k_agg1(const float* __restrict__ b1) {
    const int CH = 8;
    const int SEGS = 98;                 // 98 x 16B = 1568B per row
    const int SLOT = SEGS * 8;           // 784 halfs per row slot
    __shared__ __align__(16) __half rowbuf[2][CH][SLOT];   // 25088 B
    __shared__ float salpha[2][CH * H1N];
    __shared__ float rsum[H1N];
    int n = blockIdx.x, tid = threadIdx.x;
    int s0 = g_indptr[n], s1 = g_indptr[n + 1];
    int deg = s1 - s0;
    if (tid < H1N) rsum[tid] = __frcp_rn(g_sum1[n * H1N + tid]);
    __syncthreads();

    const __half* h1p = p_h1();
    int nt = (deg + CH - 1) / CH;

#define A1_ISSUE(T, BUF) do {                                                 \
        int base_ = (T) * CH;                                                 \
        int nc_ = min(CH, deg - base_);                                       \
        for (int q = tid; q < nc_ * SEGS; q += 256) {                         \
            int row = q / SEGS, seg = q - SEGS * row;                         \
            int src = g_csrc[s0 + base_ + row];                               \
            cp16(&rowbuf[BUF][row][seg * 8],                                  \
                 h1p + (size_t)src * H1S + seg * 8, true);                    \
        }                                                                     \
        asm volatile("cp.async.commit_group;");                               \
    } while (0)

#define A1_ALPHAS(T, BUF) do {                                                \
        int base_ = (T) * CH;                                                 \
        int nc_ = min(CH, deg - base_);                                       \
        const float* wrow = g_w1e + (size_t)(s0 + base_) * H1N;               \
        for (int p = tid; p < nc_ * H1N; p += 256)                            \
            salpha[BUF][p] = wrow[p] * rsum[p % H1N];                         \
    } while (0)

    int j0 = tid, j1 = tid + 256;
    bool has1 = (j1 < 390);
    int hA = j0 / 39, hB = has1 ? (j1 / 39) : 0;
    float a0x = 0.f, a0y = 0.f, a1x = 0.f, a1y = 0.f;

    A1_ISSUE(0, 0);
    A1_ALPHAS(0, 0);
    for (int t = 0; t < nt; t++) {
        int buf = t & 1;
        if (t + 1 < nt) {
            A1_ISSUE(t + 1, buf ^ 1);
            A1_ALPHAS(t + 1, buf ^ 1);
            asm volatile("cp.async.wait_group 1;");
        } else {
            asm volatile("cp.async.wait_group 0;");
        }
        __syncthreads();
        int nc = min(CH, deg - t * CH);
#pragma unroll 4
        for (int i = 0; i < nc; i++) {
            const __half2* hr = (const __half2*)rowbuf[buf][i];
            float aA = salpha[buf][i * H1N + hA];
            float2 f0 = __half22float2(hr[j0]);
            a0x += aA * f0.x; a0y += aA * f0.y;
            if (has1) {
                float aB = salpha[buf][i * H1N + hB];
                float2 f1 = __half22float2(hr[j1]);
                a1x += aB * f1.x; a1y += aB * f1.y;
            }
        }
        __syncthreads();
    }
#undef A1_ISSUE
#undef A1_ALPHAS

    __half2* orow = (__half2*)(p_h1e() + (size_t)n * D1P);
    float v0 = a0x + b1[2 * j0];
    float v1 = a0y + b1[2 * j0 + 1];
    v0 = (v0 > 0.f) ? v0 : (__expf(v0) - 1.f);
    v1 = (v1 > 0.f) ? v1 : (__expf(v1) - 1.f);
    orow[j0] = __floats2half2_rn(v0, v1);
    if (has1) {
        float w0 = a1x + b1[2 * j1];
        float w1 = a1y + b1[2 * j1 + 1];
        w0 = (w0 > 0.f) ? w0 : (__expf(w0) - 1.f);
        w1 = (w1 > 0.f) ? w1 : (__expf(w1) - 1.f);
        orow[j1] = __floats2half2_rn(w0, w1);
    }
    if (tid < (D1P - D1) / 2) orow[390 + tid] = __floats2half2_rn(0.f, 0.f);  // K-pad
}

// ---------------- layer2 attention coefficients: warp per node, 8 nodes/block ------
__global__ void k_attn2(const float* __restrict__ a_src, const float* __restrict__ a_dst) {
    int n = blockIdx.x * 8 + (threadIdx.x >> 5);
    if (n >= NNODES) return;
    int lane = threadIdx.x & 31;
    const float* row = p_h2() + (size_t)n * FOUT;
    float s = 0.f, d = 0.f;
#pragma unroll
    for (int j = 0; j < 4; j++) {
        int f = lane + 32 * j;
        float hv = row[f];
        s += hv * a_src[f];
        d += hv * a_dst[f];
    }
#pragma unroll
    for (int o = 16; o; o >>= 1) {
        s += __shfl_down_sync(0xffffffffu, s, o);
        d += __shfl_down_sync(0xffffffffu, d, o);
    }
    if (lane == 0) { g_als2[n] = s; g_ald2[n] = d; }
}

// ---------------- layer2 edge softmax, phases A and B -----------------------------
__global__ void k_emax2() {
    int pos = blockIdx.x * blockDim.x + threadIdx.x;
    if (pos >= ETOT) return;
    int src = g_csrc[pos], dst = g_cdst[pos];
    float e = g_als2[src] + g_ald2[dst];
    e = (e > 0.f) ? e : 0.2f * e;
    atomicMax(&g_max2[dst], fmap(e));
}

__global__ void k_esum2() {
    int pos = blockIdx.x * blockDim.x + threadIdx.x;
    if (pos >= ETOT) return;
    int src = g_csrc[pos], dst = g_cdst[pos];
    float e = g_als2[src] + g_ald2[dst];
    e = (e > 0.f) ? e : 0.2f * e;
    float w = __expf(e - funmap(g_max2[dst]));
    g_w2e[pos] = w;
    atomicAdd(&g_sum2[dst], w);
}

// ---------------- layer2 aggregate + bias + ReLU (pure gather+FMA) ----------------
__global__ void k_agg2(const float* __restrict__ b2) {
    const int CH = 128;
    __shared__ float salpha[CH];
    __shared__ int ssrc[CH];
    __shared__ float rden;
    int n = blockIdx.x, tid = threadIdx.x;
    int s0 = g_indptr[n], s1 = g_indptr[n + 1];
    int deg = s1 - s0;
    if (tid == 0) rden = __frcp_rn(g_sum2[n]);
    __syncthreads();
    const float* h2p = p_h2();
    float acc = 0.f;
    for (int base = 0; base < deg; base += CH) {
        int nc = min(CH, deg - base);
        __syncthreads();
        for (int i = tid; i < nc; i += 128) {
            ssrc[i] = g_csrc[s0 + base + i];
            salpha[i] = g_w2e[s0 + base + i] * rden;
        }
        __syncthreads();
        int i = 0;
        for (; i + 3 < nc; i += 4) {
            float v0 = h2p[(size_t)ssrc[i]     * FOUT + tid];
            float v1 = h2p[(size_t)ssrc[i + 1] * FOUT + tid];
            float v2 = h2p[(size_t)ssrc[i + 2] * FOUT + tid];
            float v3 = h2p[(size_t)ssrc[i + 3] * FOUT + tid];
            acc += salpha[i] * v0 + salpha[i + 1] * v1
                 + salpha[i + 2] * v2 + salpha[i + 3] * v3;
        }
        for (; i < nc; i++)
            acc += salpha[i] * h2p[(size_t)ssrc[i] * FOUT + tid];
    }
    float v = acc + b2[tid];
    p_h2a()[(size_t)n * FOUT + tid] = (v > 0.f) ? v : 0.f;
}

// ---------------- global max pool ----------------
__global__ void k_pool(const int* __restrict__ batch) {
    int f = threadIdx.x;               // 128
    int n0 = blockIdx.x * 16;
    if (n0 >= NNODES) return;
    int nend = min(n0 + 16, NNODES);
    const float* h2a = p_h2a();
    int b = batch[n0];
    float vmax = h2a[(size_t)n0 * FOUT + f];
    for (int n = n0 + 1; n < nend; n++) {
        int bn = batch[n];
        float v = h2a[(size_t)n * FOUT + f];
        if (bn != b) {
            atomicMax((int*)&g_pool[b * FOUT + f], __float_as_int(vmax));
            b = bn; vmax = v;
        } else {
            vmax = fmaxf(vmax, v);
        }
    }
    atomicMax((int*)&g_pool[b * FOUT + f], __float_as_int(vmax));
}

// ---------------- final FC + ReLU ----------------
__global__ void k_fc(const float* __restrict__ fc_w, const float* __restrict__ fc_b,
                     float* __restrict__ out) {
    __shared__ float gr[FOUT];
    int g = blockIdx.x, f = threadIdx.x;
    gr[f] = g_pool[g * FOUT + f];
    __syncthreads();
    float s = 0.f;
#pragma unroll 8
    for (int k = 0; k < FOUT; k++) s += gr[k] * fc_w[k * FOUT + f];
    s += fc_b[f];
    out[g * FOUT + f] = (s > 0.f) ? s : 0.f;
}

// ---------------- eager module loading via env var only ----------------
__attribute__((constructor))
static void _set_eager_module_loading() {
    setenv("CUDA_MODULE_LOADING", "EAGER", 1);
}

// ---------------- launch ----------------
extern "C" void kernel_launch(void* const* d_in, const int* in_sizes, int n_in,
                              void* d_out, int out_size) {
    const float* x      = (const float*)d_in[0];
    const int*   ei     = (const int*)  d_in[1];
    const int*   batch  = (const int*)  d_in[2];
    const float* W1     = (const float*)d_in[3];
    const float* a_src1 = (const float*)d_in[4];
    const float* a_dst1 = (const float*)d_in[5];
    const float* b1     = (const float*)d_in[6];
    const float* W2     = (const float*)d_in[7];
    const float* a_src2 = (const float*)d_in[8];
    const float* a_dst2 = (const float*)d_in[9];
    const float* b2     = (const float*)d_in[10];
    const float* fc_w   = (const float*)d_in[11];
    const float* fc_b   = (const float*)d_in[12];
    float* out = (float*)d_out;

    __half *h1, *xh, *w1h, *w2h;
    cudaGetSymbolAddress((void**)&h1,  g_arena);
    cudaGetSymbolAddress((void**)&xh,  g_xh);
    cudaGetSymbolAddress((void**)&w1h, g_w1h);
    cudaGetSymbolAddress((void**)&w2h, g_w2h);
    __half* h1e = (__half*)((unsigned char*)h1 + ARENA_H1E_OFF);
    float*  h2  = (float*)h1;

    const int EB = (ETOT + 255) / 256;

    // GEMM1 kept at my index 3 (= ncu capture slot).
    k_init<<<(NNODES * H1N + 255) / 256, 256>>>();                 // 0
    k_count<<<EB, 256>>>(ei);                                      // 1
    k_convert_all<<<2048, 256>>>(x, W1, W2);                       // 2
    {                                                              // 3: GEMM1 (ldc=H1S)
        dim3 grid((D1 + 127) / 128, (NNODES + 63) / 64);
        k_hgemm<__half><<<grid, 256>>>(xh, w1h, h1, NNODES, D1, FINP, FINP, D1P, H1S);
    }
    k_scan<<<1, 1024>>>();                                         // 4
    k_fill<<<EB, 256>>>(ei);                                       // 5
    k_attn1<<<NNODES, 320>>>(a_src1, a_dst1);                      // 6
    k_emax1<<<EB, 256>>>();                                        // 7
    k_esum1<<<EB, 256>>>();                                        // 8
    k_agg1<<<NNODES, 256>>>(b1);                                   // 9

    {                                                              // 10: GEMM2
        dim3 grid(1, (NNODES + 63) / 64);
        k_hgemm<float><<<grid, 256>>>(h1e, w2h, h2, NNODES, FOUT, D1P, D1P, FOUT, FOUT);
    }
    k_attn2<<<(NNODES + 7) / 8, 256>>>(a_src2, a_dst2);            // 11
    k_emax2<<<EB, 256>>>();                                        // 12
    k_esum2<<<EB, 256>>>();                                        // 13
    k_agg2<<<NNODES, 128>>>(b2);                                   // 14
    k_pool<<<(NNODES + 15) / 16, FOUT>>>(batch);                   // 15
    k_fc<<<NGRAPH, FOUT>>>(fc_w, fc_b, out);                       // 16
}

// round 14
// speedup vs baseline: 1.0835x; 1.0835x over previous
#include <cuda_runtime.h>
#include <cuda_fp16.h>
#include <cuda_bf16.h>
#include <cstdint>
#include <cstdlib>

#define NNODES 50000
#define E0     300000
#define ETOT   350000
#define FIN    78
#define FINP   96          // FIN padded to mult of 32
#define H1N    10
#define FH1    78
#define D1     (H1N*FH1)   // 780
#define H1S    784         // h1 row stride in halfs (1568B, 16B-aligned for cp.async)
#define D1P    800         // h1e row stride / GEMM2 K, mult of 32
#define FOUT   128
#define NGRAPH 256
#define NPB    4           // nodes per block in agg kernels (50000 % 4 == 0)

// ---------------- scratch arena (phase-aliased; static device global) ----------------
#define ARENA_H1E_OFF ((size_t)NNODES * H1S * 2)          // 78,400,000
__device__ __align__(256) unsigned char g_arena[ARENA_H1E_OFF + (size_t)NNODES * D1P * 2];

__device__ __forceinline__ __half* p_h1()  { return (__half*)g_arena; }
__device__ __forceinline__ __half* p_h1e() { return (__half*)(g_arena + ARENA_H1E_OFF); }
__device__ __forceinline__ float*  p_h2()  { return (float*)g_arena; }
__device__ __forceinline__ float*  p_h2a() { return (float*)(g_arena + ARENA_H1E_OFF); }

__device__ __align__(16) __half g_xh [(size_t)NNODES * FINP];        // x fp16, K-padded
__device__ __align__(16) __half g_w1h[(size_t)FINP * D1P + 4096];    // W1 fp16 [96][800]
__device__ __align__(16) __half g_w2h[(size_t)D1P * FOUT + 4096];    // W2 fp16 [800][128]

__device__ float g_als1[NNODES * H1N];
__device__ float g_ald1[NNODES * H1N];
__device__ float g_als2[NNODES];
__device__ float g_ald2[NNODES];
__device__ int   g_cnt[NNODES];
__device__ int   g_indptr[NNODES + 1];
__device__ int   g_cursor[NNODES];
__device__ int   g_csrc[ETOT];
__device__ float g_pool[NGRAPH * FOUT];

// monotone float<->uint map for atomicMax on floats (handles negatives)
__device__ __forceinline__ unsigned fmap(float f) {
    unsigned u = __float_as_uint(f);
    return (u & 0x80000000u) ? ~u : (u | 0x80000000u);
}
__device__ __forceinline__ float funmap(unsigned u) {
    return __uint_as_float((u & 0x80000000u) ? (u & 0x7fffffffu) : ~u);
}

__device__ __forceinline__ void cp16(void* sm, const void* gm, bool pred) {
    uint32_t s = (uint32_t)__cvta_generic_to_shared(sm);
    int sz = pred ? 16 : 0;
    asm volatile("cp.async.cg.shared.global [%0], [%1], 16, %2;" :: "r"(s), "l"(gm), "r"(sz));
}

// vector C-store helpers
__device__ __forceinline__ void st2(__half* p, float a, float b) {
    *(__half2*)p = __floats2half2_rn(a, b);
}
__device__ __forceinline__ void st2(float* p, float a, float b) {
    *(float2*)p = make_float2(a, b);
}

// ---------------- init: zero counts + pool ----------------
__global__ void k_init() {
    int i = blockIdx.x * blockDim.x + threadIdx.x;
    if (i < NNODES) g_cnt[i] = 0;
    if (i < NGRAPH * FOUT) g_pool[i] = 0.0f;
}

// ---------------- CSR build ----------------
__global__ void k_count(const int* __restrict__ ei) {
    int e = blockIdx.x * blockDim.x + threadIdx.x;
    if (e >= ETOT) return;
    int dst = (e < E0) ? ei[E0 + e] : (e - E0);
    atomicAdd(&g_cnt[dst], 1);
}

__global__ void k_scan() {  // single block, 1024 threads
    const int ITEMS = (NNODES + 1023) / 1024;   // 49
    int t = threadIdx.x;
    int base = t * ITEMS;
    int sum = 0;
    for (int k = 0; k < ITEMS; k++) {
        int idx = base + k;
        if (idx < NNODES) sum += g_cnt[idx];
    }
    __shared__ int sh[1024];
    sh[t] = sum;
    __syncthreads();
    for (int off = 1; off < 1024; off <<= 1) {
        int v = (t >= off) ? sh[t - off] : 0;
        __syncthreads();
        sh[t] += v;
        __syncthreads();
    }
    int run = (t > 0) ? sh[t - 1] : 0;
    for (int k = 0; k < ITEMS; k++) {
        int idx = base + k;
        if (idx < NNODES) {
            g_indptr[idx] = run;
            g_cursor[idx] = run;
            run += g_cnt[idx];
        }
    }
    if (t == 1023) g_indptr[NNODES] = sh[1023];
}

__global__ void k_fill(const int* __restrict__ ei) {
    int e = blockIdx.x * blockDim.x + threadIdx.x;
    if (e >= ETOT) return;
    int src, dst;
    if (e < E0) { src = ei[e]; dst = ei[E0 + e]; }
    else        { src = e - E0; dst = e - E0; }
    int pos = atomicAdd(&g_cursor[dst], 1);
    g_csrc[pos] = src;
}

// ---------------- fused fp32->fp16 conversion of x, W1, W2 (K-padded) -------------
__global__ void k_convert_all(const float* __restrict__ x, const float* __restrict__ W1,
                              const float* __restrict__ W2) {
    const int NX = NNODES * FINP;
    const int NW1 = FINP * D1P;
    const int NW2 = D1P * FOUT;
    int i = blockIdx.x * blockDim.x + threadIdx.x;
    int stride = gridDim.x * blockDim.x;
    for (int idx = i; idx < NX + NW1 + NW2; idx += stride) {
        if (idx < NX) {
            int r = idx / FINP, c = idx - r * FINP;
            float v = (c < FIN) ? x[(size_t)r * FIN + c] : 0.0f;
            g_xh[idx] = __float2half(v);
        } else if (idx < NX + NW1) {
            int j = idx - NX;
            int r = j / D1P, c = j - r * D1P;
            float v = (r < FIN && c < D1) ? W1[(size_t)r * D1 + c] : 0.0f;
            g_w1h[j] = __float2half(v);
        } else {
            int j = idx - NX - NW1;
            int r = j / FOUT, c = j - r * FOUT;
            float v = (r < D1) ? W2[(size_t)r * FOUT + c] : 0.0f;
            g_w2h[j] = __float2half(v);
        }
    }
}

// ---------------- tensor-core GEMM (BM=64, BN=128, BK=32, 3 CTA/SM) -------------
template<typename TC>
__global__ void __launch_bounds__(256, 3)
k_hgemm(const __half* __restrict__ A, const __half* __restrict__ B,
        TC* __restrict__ C, int M, int Nn, int K,
        int lda, int ldb, int ldc) {
    const int BM = 64, BK = 32;
    const int ASW = 40;
    const int BSW = 136;
    __shared__ __half As[2][BM * ASW];
    __shared__ __half Bs[2][BK * BSW];
    int tid = threadIdx.x, lane = tid & 31, warp = tid >> 5;
    int wm = (warp & 1) * 32, wn = (warp >> 1) * 32;
    int m0 = blockIdx.y * BM, n0 = blockIdx.x * 128;

    float acc[2][4][4];
#pragma unroll
    for (int a = 0; a < 2; a++)
#pragma unroll
        for (int b = 0; b < 4; b++)
#pragma unroll
            for (int c = 0; c < 4; c++) acc[a][b][c] = 0.f;

    const int ntiles = K / BK;

#define ISSUE_TILE(T, BUF) do {                                              \
        int kt_ = (T) * BK;                                                  \
        {                                                                    \
            int r = tid >> 2, c16 = (tid & 3) * 8;                           \
            int gm = m0 + r;                                                 \
            cp16(&As[BUF][r * ASW + c16], A + (size_t)gm * lda + kt_ + c16,  \
                 gm < M);                                                    \
        }                                                                    \
        _Pragma("unroll")                                                    \
        for (int q = 0; q < 2; q++) {                                        \
            int idx = tid + q * 256;                                         \
            int r = idx >> 4, c16 = (idx & 15) * 8;                          \
            int gn = n0 + c16;                                               \
            cp16(&Bs[BUF][r * BSW + c16], B + (size_t)(kt_ + r) * ldb + gn,  \
                 gn + 8 <= ldb);                                             \
        }                                                                    \
        asm volatile("cp.async.commit_group;");                              \
    } while (0)

    ISSUE_TILE(0, 0);
    for (int t = 0; t < ntiles; t++) {
        int buf = t & 1;
        if (t + 1 < ntiles) {
            ISSUE_TILE(t + 1, buf ^ 1);
            asm volatile("cp.async.wait_group 1;");
        } else {
            asm volatile("cp.async.wait_group 0;");
        }
        __syncthreads();

        const __half* as = As[buf];
        const __half* bs = Bs[buf];
#pragma unroll
        for (int ks = 0; ks < 2; ks++) {
            int kk = ks * 16;
            uint32_t af[2][4];
#pragma unroll
            for (int mf = 0; mf < 2; mf++) {
                int g = lane >> 3, j = lane & 7;
                int row = wm + mf * 16 + j + ((g & 1) << 3);
                int col = kk + ((g >> 1) << 3);
                uint32_t addr = (uint32_t)__cvta_generic_to_shared(as + row * ASW + col);
                asm volatile(
                    "ldmatrix.sync.aligned.m8n8.x4.shared.b16 {%0,%1,%2,%3}, [%4];"
                    : "=r"(af[mf][0]), "=r"(af[mf][1]), "=r"(af[mf][2]), "=r"(af[mf][3])
                    : "r"(addr));
            }
            uint32_t bf[4][2];
#pragma unroll
            for (int nfp = 0; nfp < 2; nfp++) {
                int nn0 = wn + nfp * 16;
                int g = lane >> 3, j = lane & 7;
                int row = kk + j + ((g & 1) << 3);
                int col = nn0 + ((g >> 1) << 3);
                uint32_t addr = (uint32_t)__cvta_generic_to_shared(bs + row * BSW + col);
                asm volatile(
                    "ldmatrix.sync.aligned.m8n8.x4.trans.shared.b16 {%0,%1,%2,%3}, [%4];"
                    : "=r"(bf[2 * nfp][0]), "=r"(bf[2 * nfp][1]),
                      "=r"(bf[2 * nfp + 1][0]), "=r"(bf[2 * nfp + 1][1])
                    : "r"(addr));
            }
#pragma unroll
            for (int mf = 0; mf < 2; mf++)
#pragma unroll
                for (int nf = 0; nf < 4; nf++) {
                    float* c = acc[mf][nf];
                    asm volatile(
                        "mma.sync.aligned.m16n8k16.row.col.f32.f16.f16.f32 "
                        "{%0,%1,%2,%3}, {%4,%5,%6,%7}, {%8,%9}, {%0,%1,%2,%3};"
                        : "+f"(c[0]), "+f"(c[1]), "+f"(c[2]), "+f"(c[3])
                        : "r"(af[mf][0]), "r"(af[mf][1]), "r"(af[mf][2]), "r"(af[mf][3]),
                          "r"(bf[nf][0]), "r"(bf[nf][1]));
                }
        }
        __syncthreads();
    }
#undef ISSUE_TILE

#pragma unroll
    for (int mf = 0; mf < 2; mf++)
#pragma unroll
        for (int nf = 0; nf < 4; nf++) {
            int r = m0 + wm + mf * 16 + (lane >> 2);
            int cbase = n0 + wn + nf * 8 + (lane & 3) * 2;
            const float* c = acc[mf][nf];
            if (cbase < Nn) {
                if (r < M)     st2(C + (size_t)r * ldc + cbase,       c[0], c[1]);
                if (r + 8 < M) st2(C + (size_t)(r + 8) * ldc + cbase, c[2], c[3]);
            }
        }
}

// ---------------- layer1 attention coefficients: warp per (node,head), half2 -------
__global__ void k_attn1(const float* __restrict__ a_src, const float* __restrict__ a_dst) {
    int n = blockIdx.x;
    int w = threadIdx.x >> 5;
    int lane = threadIdx.x & 31;
    const __half2* row = (const __half2*)(p_h1() + (size_t)n * H1S + w * FH1);
    const float* asw = a_src + w * FH1;
    const float* adw = a_dst + w * FH1;
    float s = 0.f, d = 0.f;
#pragma unroll
    for (int j = lane; j < 39; j += 32) {
        float2 f = __half22float2(row[j]);
        s += f.x * asw[2 * j] + f.y * asw[2 * j + 1];
        d += f.x * adw[2 * j] + f.y * adw[2 * j + 1];
    }
#pragma unroll
    for (int o = 16; o; o >>= 1) {
        s += __shfl_down_sync(0xffffffffu, s, o);
        d += __shfl_down_sync(0xffffffffu, d, o);
    }
    if (lane == 0) {
        g_als1[n * H1N + w] = s;
        g_ald1[n * H1N + w] = d;
    }
}

// ---------------- layer1: softmax + aggregate + bias + ELU, 4 nodes per block ------
// Consecutive nodes have contiguous CSR ranges -> one contiguous edge group
// (~28 edges avg = 3-4 pipeline chunks), so the cp.async double-buffer actually
// overlaps. Per-node accumulation via a running pair flushed on node change
// (warp-uniform branch; edges are sorted by node in CSR order).
__global__ void k_agg1(const float* __restrict__ b1) {
    const int CH = 8;
    const int SEGS = 98;                 // 98 x 16B = 1568B per row
    const int SLOT = SEGS * 8;           // 784 halfs per row slot
    __shared__ __align__(16) __half rowbuf[2][CH][SLOT];   // 25088 B
    __shared__ float salpha[2][CH * H1N];
    __shared__ int   slid[2][CH];
    __shared__ float ald[NPB * H1N];
    __shared__ unsigned umax[NPB * H1N];
    __shared__ float smax[NPB * H1N];
    __shared__ float ssum[NPB * H1N];
    __shared__ float rsum[NPB * H1N];
    __shared__ int sind[NPB + 1];
    int n0 = blockIdx.x * NPB, tid = threadIdx.x;
    if (tid < NPB * H1N) {
        ald[tid] = g_ald1[n0 * H1N + tid];   // contiguous across the 4 nodes
        umax[tid] = 0u;
        ssum[tid] = 0.f;
    }
    if (tid < NPB + 1) sind[tid] = g_indptr[n0 + tid];
    __syncthreads();
    int S0 = sind[0];
    int e1 = sind[1] - S0, e2 = sind[2] - S0, e3 = sind[3] - S0;
    int G = sind[NPB] - S0;
    int P = G * H1N;
    for (int p = tid; p < P; p += 256) {
        int i = p / H1N, h = p - H1N * i;
        int l = (i >= e1) + (i >= e2) + (i >= e3);
        int src = g_csrc[S0 + i];
        float e = g_als1[src * H1N + h] + ald[l * H1N + h];
        e = (e > 0.f) ? e : 0.2f * e;
        atomicMax(&umax[l * H1N + h], fmap(e));
    }
    __syncthreads();
    if (tid < NPB * H1N) smax[tid] = funmap(umax[tid]);
    __syncthreads();
    for (int p = tid; p < P; p += 256) {
        int i = p / H1N, h = p - H1N * i;
        int l = (i >= e1) + (i >= e2) + (i >= e3);
        int src = g_csrc[S0 + i];
        float e = g_als1[src * H1N + h] + ald[l * H1N + h];
        e = (e > 0.f) ? e : 0.2f * e;
        atomicAdd(&ssum[l * H1N + h], __expf(e - smax[l * H1N + h]));
    }
    __syncthreads();
    if (tid < NPB * H1N) rsum[tid] = __frcp_rn(ssum[tid]);
    __syncthreads();

    const __half* h1p = p_h1();
    int nt = (G + CH - 1) / CH;

#define A1_ISSUE(T, BUF) do {                                                 \
        int base_ = (T) * CH;                                                 \
        int nc_ = min(CH, G - base_);                                         \
        for (int q = tid; q < nc_ * SEGS; q += 256) {                         \
            int row = q / SEGS, seg = q - SEGS * row;                         \
            int src = g_csrc[S0 + base_ + row];                               \
            cp16(&rowbuf[BUF][row][seg * 8],                                  \
                 h1p + (size_t)src * H1S + seg * 8, true);                    \
        }                                                                     \
        asm volatile("cp.async.commit_group;");                               \
    } while (0)

#define A1_ALPHAS(T, BUF) do {                                                \
        int base_ = (T) * CH;                                                 \
        int nc_ = min(CH, G - base_);                                         \
        if (tid < nc_) {                                                      \
            int gi = base_ + tid;                                             \
            slid[BUF][tid] = (gi >= e1) + (gi >= e2) + (gi >= e3);            \
        }                                                                     \
        for (int p = tid; p < nc_ * H1N; p += 256) {                          \
            int i = p / H1N, h = p - H1N * i;                                 \
            int gi = base_ + i;                                               \
            int l = (gi >= e1) + (gi >= e2) + (gi >= e3);                     \
            int src = g_csrc[S0 + gi];                                        \
            float e = g_als1[src * H1N + h] + ald[l * H1N + h];               \
            e = (e > 0.f) ? e : 0.2f * e;                                     \
            salpha[BUF][p] = __expf(e - smax[l * H1N + h]) * rsum[l * H1N + h]; \
        }                                                                     \
    } while (0)

    int j0 = tid, j1 = tid + 256;
    bool has1 = (j1 < 390);
    int hA = j0 / 39, hB = has1 ? (j1 / 39) : 0;
    float a0x[NPB], a0y[NPB], a1x[NPB], a1y[NPB];
#pragma unroll
    for (int l = 0; l < NPB; l++) { a0x[l] = a0y[l] = a1x[l] = a1y[l] = 0.f; }
    float c0x = 0.f, c0y = 0.f, c1x = 0.f, c1y = 0.f;
    int curl = -1;

#define A1_FLUSH() do {                                                       \
        _Pragma("unroll")                                                     \
        for (int l = 0; l < NPB; l++)                                         \
            if (l == curl) {                                                  \
                a0x[l] += c0x; a0y[l] += c0y;                                 \
                a1x[l] += c1x; a1y[l] += c1y;                                 \
            }                                                                 \
        c0x = c0y = c1x = c1y = 0.f;                                          \
    } while (0)

    A1_ISSUE(0, 0);
    A1_ALPHAS(0, 0);
    for (int t = 0; t < nt; t++) {
        int buf = t & 1;
        if (t + 1 < nt) {
            A1_ISSUE(t + 1, buf ^ 1);
            A1_ALPHAS(t + 1, buf ^ 1);
            asm volatile("cp.async.wait_group 1;");
        } else {
            asm volatile("cp.async.wait_group 0;");
        }
        __syncthreads();
        int nc = min(CH, G - t * CH);
#pragma unroll 4
        for (int i = 0; i < nc; i++) {
            int l = slid[buf][i];
            if (l != curl) { A1_FLUSH(); curl = l; }   // warp-uniform branch
            const __half2* hr = (const __half2*)rowbuf[buf][i];
            float aA = salpha[buf][i * H1N + hA];
            float2 f0 = __half22float2(hr[j0]);
            c0x += aA * f0.x; c0y += aA * f0.y;
            if (has1) {
                float aB = salpha[buf][i * H1N + hB];
                float2 f1 = __half22float2(hr[j1]);
                c1x += aB * f1.x; c1y += aB * f1.y;
            }
        }
        __syncthreads();
    }
    A1_FLUSH();
#undef A1_ISSUE
#undef A1_ALPHAS
#undef A1_FLUSH

    float bb0 = b1[2 * j0], bb1 = b1[2 * j0 + 1];
    float bb2 = 0.f, bb3 = 0.f;
    if (has1) { bb2 = b1[2 * j1]; bb3 = b1[2 * j1 + 1]; }
#pragma unroll
    for (int l = 0; l < NPB; l++) {
        __half2* orow = (__half2*)(p_h1e() + (size_t)(n0 + l) * D1P);
        float v0 = a0x[l] + bb0, v1 = a0y[l] + bb1;
        v0 = (v0 > 0.f) ? v0 : (__expf(v0) - 1.f);
        v1 = (v1 > 0.f) ? v1 : (__expf(v1) - 1.f);
        orow[j0] = __floats2half2_rn(v0, v1);
        if (has1) {
            float w0 = a1x[l] + bb2, w1 = a1y[l] + bb3;
            w0 = (w0 > 0.f) ? w0 : (__expf(w0) - 1.f);
            w1 = (w1 > 0.f) ? w1 : (__expf(w1) - 1.f);
            orow[j1] = __floats2half2_rn(w0, w1);
        }
        if (tid < (D1P - D1) / 2) orow[390 + tid] = __floats2half2_rn(0.f, 0.f);
    }
}

// ---------------- layer2 attention coefficients: warp per node, 8 nodes/block ------
__global__ void k_attn2(const float* __restrict__ a_src, const float* __restrict__ a_dst) {
    int n = blockIdx.x * 8 + (threadIdx.x >> 5);
    if (n >= NNODES) return;
    int lane = threadIdx.x & 31;
    const float* row = p_h2() + (size_t)n * FOUT;
    float s = 0.f, d = 0.f;
#pragma unroll
    for (int j = 0; j < 4; j++) {
        int f = lane + 32 * j;
        float hv = row[f];
        s += hv * a_src[f];
        d += hv * a_dst[f];
    }
#pragma unroll
    for (int o = 16; o; o >>= 1) {
        s += __shfl_down_sync(0xffffffffu, s, o);
        d += __shfl_down_sync(0xffffffffu, d, o);
    }
    if (lane == 0) { g_als2[n] = s; g_ald2[n] = d; }
}

// ---------------- layer2: softmax + aggregate + bias + ReLU, 4 nodes per block -----
__global__ void k_agg2(const float* __restrict__ b2) {
    const int CH = 32;
    __shared__ float salpha[CH];
    __shared__ int ssrc_s[CH];
    __shared__ int slid[CH];
    __shared__ float ald[NPB];
    __shared__ unsigned umax[NPB];
    __shared__ float smax[NPB];
    __shared__ float ssum[NPB];
    __shared__ float rsum[NPB];
    __shared__ int sind[NPB + 1];
    int n0 = blockIdx.x * NPB, tid = threadIdx.x;   // 128 threads
    if (tid < NPB) { ald[tid] = g_ald2[n0 + tid]; umax[tid] = 0u; ssum[tid] = 0.f; }
    if (tid < NPB + 1) sind[tid] = g_indptr[n0 + tid];
    __syncthreads();
    int S0 = sind[0];
    int e1 = sind[1] - S0, e2 = sind[2] - S0, e3 = sind[3] - S0;
    int G = sind[NPB] - S0;
    for (int i = tid; i < G; i += 128) {
        int l = (i >= e1) + (i >= e2) + (i >= e3);
        float e = g_als2[g_csrc[S0 + i]] + ald[l];
        e = (e > 0.f) ? e : 0.2f * e;
        atomicMax(&umax[l], fmap(e));
    }
    __syncthreads();
    if (tid < NPB) smax[tid] = funmap(umax[tid]);
    __syncthreads();
    for (int i = tid; i < G; i += 128) {
        int l = (i >= e1) + (i >= e2) + (i >= e3);
        float e = g_als2[g_csrc[S0 + i]] + ald[l];
        e = (e > 0.f) ? e : 0.2f * e;
        atomicAdd(&ssum[l], __expf(e - smax[l]));
    }
    __syncthreads();
    if (tid < NPB) rsum[tid] = __frcp_rn(ssum[tid]);
    __syncthreads();

    const float* h2p = p_h2();
    float acc[NPB];
#pragma unroll
    for (int l = 0; l < NPB; l++) acc[l] = 0.f;
    float cur = 0.f;
    int curl = -1;

#define A2_FLUSH() do {                                                       \
        _Pragma("unroll")                                                     \
        for (int l = 0; l < NPB; l++)                                         \
            if (l == curl) acc[l] += cur;                                     \
        cur = 0.f;                                                            \
    } while (0)

    for (int base = 0; base < G; base += CH) {
        int nc = min(CH, G - base);
        __syncthreads();
        for (int i = tid; i < nc; i += 128) {
            int gi = base + i;
            int l = (gi >= e1) + (gi >= e2) + (gi >= e3);
            int src = g_csrc[S0 + gi];
            ssrc_s[i] = src;
            slid[i] = l;
            float e = g_als2[src] + ald[l];
            e = (e > 0.f) ? e : 0.2f * e;
            salpha[i] = __expf(e - smax[l]) * rsum[l];
        }
        __syncthreads();
        int i = 0;
        for (; i + 3 < nc; i += 4) {
            float v[4];
            v[0] = h2p[(size_t)ssrc_s[i]     * FOUT + tid];
            v[1] = h2p[(size_t)ssrc_s[i + 1] * FOUT + tid];
            v[2] = h2p[(size_t)ssrc_s[i + 2] * FOUT + tid];
            v[3] = h2p[(size_t)ssrc_s[i + 3] * FOUT + tid];
#pragma unroll
            for (int k = 0; k < 4; k++) {
                int l = slid[i + k];
                if (l != curl) { A2_FLUSH(); curl = l; }
                cur += salpha[i + k] * v[k];
            }
        }
        for (; i < nc; i++) {
            int l = slid[i];
            if (l != curl) { A2_FLUSH(); curl = l; }
            cur += salpha[i] * h2p[(size_t)ssrc_s[i] * FOUT + tid];
        }
    }
    A2_FLUSH();
#undef A2_FLUSH

    float bb = b2[tid];
#pragma unroll
    for (int l = 0; l < NPB; l++) {
        float v = acc[l] + bb;
        p_h2a()[(size_t)(n0 + l) * FOUT + tid] = (v > 0.f) ? v : 0.f;
    }
}

// ---------------- global max pool ----------------
__global__ void k_pool(const int* __restrict__ batch) {
    int f = threadIdx.x;               // 128
    int n0 = blockIdx.x * 16;
    if (n0 >= NNODES) return;
    int nend = min(n0 + 16, NNODES);
    const float* h2a = p_h2a();
    int b = batch[n0];
    float vmax = h2a[(size_t)n0 * FOUT + f];
    for (int n = n0 + 1; n < nend; n++) {
        int bn = batch[n];
        float v = h2a[(size_t)n * FOUT + f];
        if (bn != b) {
            atomicMax((int*)&g_pool[b * FOUT + f], __float_as_int(vmax));
            b = bn; vmax = v;
        } else {
            vmax = fmaxf(vmax, v);
        }
    }
    atomicMax((int*)&g_pool[b * FOUT + f], __float_as_int(vmax));
}

// ---------------- final FC + ReLU ----------------
__global__ void k_fc(const float* __restrict__ fc_w, const float* __restrict__ fc_b,
                     float* __restrict__ out) {
    __shared__ float gr[FOUT];
    int g = blockIdx.x, f = threadIdx.x;
    gr[f] = g_pool[g * FOUT + f];
    __syncthreads();
    float s = 0.f;
#pragma unroll 8
    for (int k = 0; k < FOUT; k++) s += gr[k] * fc_w[k * FOUT + f];
    s += fc_b[f];
    out[g * FOUT + f] = (s > 0.f) ? s : 0.f;
}

// ---------------- eager module loading via env var only ----------------
__attribute__((constructor))
static void _set_eager_module_loading() {
    setenv("CUDA_MODULE_LOADING", "EAGER", 1);
}

// ---------------- launch ----------------
extern "C" void kernel_launch(void* const* d_in, const int* in_sizes, int n_in,
                              void* d_out, int out_size) {
    const float* x      = (const float*)d_in[0];
    const int*   ei     = (const int*)  d_in[1];
    const int*   batch  = (const int*)  d_in[2];
    const float* W1     = (const float*)d_in[3];
    const float* a_src1 = (const float*)d_in[4];
    const float* a_dst1 = (const float*)d_in[5];
    const float* b1     = (const float*)d_in[6];
    const float* W2     = (const float*)d_in[7];
    const float* a_src2 = (const float*)d_in[8];
    const float* a_dst2 = (const float*)d_in[9];
    const float* b2     = (const float*)d_in[10];
    const float* fc_w   = (const float*)d_in[11];
    const float* fc_b   = (const float*)d_in[12];
    float* out = (float*)d_out;

    __half *h1, *xh, *w1h, *w2h;
    cudaGetSymbolAddress((void**)&h1,  g_arena);
    cudaGetSymbolAddress((void**)&xh,  g_xh);
    cudaGetSymbolAddress((void**)&w1h, g_w1h);
    cudaGetSymbolAddress((void**)&w2h, g_w2h);
    __half* h1e = (__half*)((unsigned char*)h1 + ARENA_H1E_OFF);
    float*  h2  = (float*)h1;

    const int EB = (ETOT + 255) / 256;

    // GEMM1 kept at my index 3 (= ncu capture slot).
    k_init<<<(NGRAPH * FOUT + 255) / 256 > (NNODES + 255) / 256 ?
             (NGRAPH * FOUT + 255) / 256 : (NNODES + 255) / 256, 256>>>();   // 0
    k_count<<<EB, 256>>>(ei);                                      // 1
    k_convert_all<<<2048, 256>>>(x, W1, W2);                       // 2
    {                                                              // 3: GEMM1 (ldc=H1S)
        dim3 grid((D1 + 127) / 128, (NNODES + 63) / 64);
        k_hgemm<__half><<<grid, 256>>>(xh, w1h, h1, NNODES, D1, FINP, FINP, D1P, H1S);
    }
    k_scan<<<1, 1024>>>();                                         // 4
    k_fill<<<EB, 256>>>(ei);                                       // 5
    k_attn1<<<NNODES, 320>>>(a_src1, a_dst1);                      // 6
    k_agg1<<<NNODES / NPB, 256>>>(b1);                             // 7

    {                                                              // 8: GEMM2
        dim3 grid(1, (NNODES + 63) / 64);
        k_hgemm<float><<<grid, 256>>>(h1e, w2h, h2, NNODES, FOUT, D1P, D1P, FOUT, FOUT);
    }
    k_attn2<<<(NNODES + 7) / 8, 256>>>(a_src2, a_dst2);            // 9
    k_agg2<<<NNODES / NPB, 128>>>(b2);                             // 10
    k_pool<<<(NNODES + 15) / 16, FOUT>>>(batch);                   // 11
    k_fc<<<NGRAPH, FOUT>>>(fc_w, fc_b, out);                       // 12
}